// round 16
// baseline (speedup 1.0000x reference)
#include <cuda_runtime.h>
#include <cuda_bf16.h>
#include <cstdint>
#include <math.h>

typedef unsigned int u32;

// Problem constants
#define LNUM 6
#define BB   8
#define TT   1024
#define SS   1024
#define EE   1024
#define HH   16
#define HDIM 64
#define FF   4096
#define MROWS (BB*TT)
#define LN_EPS 1e-5f

// ---------------------------------------------------------------------------
// Scratch (device globals; no allocation allowed)
// ---------------------------------------------------------------------------
__device__ __nv_bfloat16 g_qh  [(size_t)MROWS*EE];
__device__ __nv_bfloat16 g_ql  [(size_t)MROWS*EE];
__device__ __nv_bfloat16 g_kh  [(size_t)MROWS*EE];
__device__ __nv_bfloat16 g_kl  [(size_t)MROWS*EE];
__device__ __nv_bfloat16 g_vh  [(size_t)MROWS*EE];
__device__ __nv_bfloat16 g_vl  [(size_t)MROWS*EE];
__device__ __nv_bfloat16 g_nxh [(size_t)MROWS*EE];
__device__ __nv_bfloat16 g_nxl [(size_t)MROWS*EE];
__device__ __nv_bfloat16 g_ench[(size_t)MROWS*EE];
__device__ __nv_bfloat16 g_encl[(size_t)MROWS*EE];
__device__ __nv_bfloat16 g_ath [(size_t)MROWS*EE];
__device__ __nv_bfloat16 g_atl [(size_t)MROWS*EE];
__device__ __nv_bfloat16 g_ffh [(size_t)MROWS*FF];
__device__ __nv_bfloat16 g_ffl [(size_t)MROWS*FF];
__device__ __nv_bfloat16 g_wh  [(size_t)EE*FF];
__device__ __nv_bfloat16 g_wl  [(size_t)EE*FF];

// ---------------------------------------------------------------------------
// Common device helpers
// ---------------------------------------------------------------------------
__device__ __forceinline__ float gelu_tanh(float x) {
    float x3 = x * x * x;
    return 0.5f * x * (1.f + tanhf(0.79788456080286535588f * (x + 0.044715f * x3)));
}
__device__ __forceinline__ void ldsm_x4(u32* r, u32 a) {
    asm volatile("ldmatrix.sync.aligned.m8n8.x4.shared.b16 {%0,%1,%2,%3}, [%4];"
                 : "=r"(r[0]), "=r"(r[1]), "=r"(r[2]), "=r"(r[3]) : "r"(a));
}
__device__ __forceinline__ void ldsm_x4t(u32* r, u32 a) {
    asm volatile("ldmatrix.sync.aligned.m8n8.x4.trans.shared.b16 {%0,%1,%2,%3}, [%4];"
                 : "=r"(r[0]), "=r"(r[1]), "=r"(r[2]), "=r"(r[3]) : "r"(a));
}
__device__ __forceinline__ void mma_bf16(float* c, const u32* a, u32 b0, u32 b1) {
    asm volatile(
        "mma.sync.aligned.m16n8k16.row.col.f32.bf16.bf16.f32 "
        "{%0,%1,%2,%3}, {%4,%5,%6,%7}, {%8,%9}, {%0,%1,%2,%3};"
        : "+f"(c[0]), "+f"(c[1]), "+f"(c[2]), "+f"(c[3])
        : "r"(a[0]), "r"(a[1]), "r"(a[2]), "r"(a[3]), "r"(b0), "r"(b1));
}
__device__ __forceinline__ void cp16(u32 dst, const void* src) {
    asm volatile("cp.async.cg.shared.global [%0], [%1], 16;\n" :: "r"(dst), "l"(src));
}
__device__ __forceinline__ void cp_commit() {
    asm volatile("cp.async.commit_group;\n");
}
template<int N>
__device__ __forceinline__ void cp_wait() {
    asm volatile("cp.async.wait_group %0;\n" :: "n"(N));
}
__device__ __forceinline__ u32 packbf(float x, float y) {
    __nv_bfloat162 t = __halves2bfloat162(__float2bfloat16(x), __float2bfloat16(y));
    return *(u32*)&t;
}

// ---------------------------------------------------------------------------
// Elementwise fp32 -> bf16 (hi, lo) splitter. n multiple of 1024.
// ---------------------------------------------------------------------------
__global__ void __launch_bounds__(256) split_kernel(
    const float* __restrict__ in,
    __nv_bfloat16* __restrict__ hi, __nv_bfloat16* __restrict__ lo)
{
    size_t i = ((size_t)blockIdx.x * 256 + threadIdx.x) * 4;
    float4 v = *(const float4*)(in + i);
    __nv_bfloat16 h0 = __float2bfloat16(v.x);
    __nv_bfloat16 h1 = __float2bfloat16(v.y);
    __nv_bfloat16 h2 = __float2bfloat16(v.z);
    __nv_bfloat16 h3 = __float2bfloat16(v.w);
    __nv_bfloat16 l0 = __float2bfloat16(v.x - __bfloat162float(h0));
    __nv_bfloat16 l1 = __float2bfloat16(v.y - __bfloat162float(h1));
    __nv_bfloat16 l2 = __float2bfloat16(v.z - __bfloat162float(h2));
    __nv_bfloat16 l3 = __float2bfloat16(v.w - __bfloat162float(h3));
    *(__nv_bfloat162*)(hi + i)     = __halves2bfloat162(h0, h1);
    *(__nv_bfloat162*)(hi + i + 2) = __halves2bfloat162(h2, h3);
    *(__nv_bfloat162*)(lo + i)     = __halves2bfloat162(l0, l1);
    *(__nv_bfloat162*)(lo + i + 2) = __halves2bfloat162(l2, l3);
}

// ---------------------------------------------------------------------------
// LayerNorm -> bf16 hi/lo outputs
// ---------------------------------------------------------------------------
__global__ void __launch_bounds__(256) layernorm_kernel(
    const float* __restrict__ x, const float* __restrict__ w,
    const float* __restrict__ b,
    __nv_bfloat16* __restrict__ oh, __nv_bfloat16* __restrict__ ol)
{
    const int row = blockIdx.x;
    const int tid = threadIdx.x;
    const float4* xr = (const float4*)(x + (size_t)row * EE);
    float4 xv = xr[tid];
    float s  = xv.x + xv.y + xv.z + xv.w;
    float sq = xv.x*xv.x + xv.y*xv.y + xv.z*xv.z + xv.w*xv.w;
    #pragma unroll
    for (int o = 16; o > 0; o >>= 1) {
        s  += __shfl_down_sync(0xffffffffu, s,  o);
        sq += __shfl_down_sync(0xffffffffu, sq, o);
    }
    __shared__ float ss[8];
    __shared__ float ssq[8];
    __shared__ float mean_s, rstd_s;
    const int wid = tid >> 5;
    const int lane = tid & 31;
    if (lane == 0) { ss[wid] = s; ssq[wid] = sq; }
    __syncthreads();
    if (tid == 0) {
        float ts = 0.f, tq = 0.f;
        #pragma unroll
        for (int i = 0; i < 8; i++) { ts += ss[i]; tq += ssq[i]; }
        float m   = ts * (1.f / EE);
        float var = tq * (1.f / EE) - m * m;
        mean_s = m;
        rstd_s = rsqrtf(var + LN_EPS);
    }
    __syncthreads();
    const float m = mean_s;
    const float r = rstd_s;
    float4 wv = ((const float4*)w)[tid];
    float4 bv = ((const float4*)b)[tid];
    float o0 = (xv.x - m) * r * wv.x + bv.x;
    float o1 = (xv.y - m) * r * wv.y + bv.y;
    float o2 = (xv.z - m) * r * wv.z + bv.z;
    float o3 = (xv.w - m) * r * wv.w + bv.w;
    __nv_bfloat16 h0 = __float2bfloat16(o0);
    __nv_bfloat16 h1 = __float2bfloat16(o1);
    __nv_bfloat16 h2 = __float2bfloat16(o2);
    __nv_bfloat16 h3 = __float2bfloat16(o3);
    __nv_bfloat16 l0 = __float2bfloat16(o0 - __bfloat162float(h0));
    __nv_bfloat16 l1 = __float2bfloat16(o1 - __bfloat162float(h1));
    __nv_bfloat16 l2 = __float2bfloat16(o2 - __bfloat162float(h2));
    __nv_bfloat16 l3 = __float2bfloat16(o3 - __bfloat162float(h3));
    size_t o = (size_t)row * EE + tid * 4;
    *(__nv_bfloat162*)(oh + o)     = __halves2bfloat162(h0, h1);
    *(__nv_bfloat162*)(oh + o + 2) = __halves2bfloat162(h2, h3);
    *(__nv_bfloat162*)(ol + o)     = __halves2bfloat162(l0, l1);
    *(__nv_bfloat162*)(ol + o + 2) = __halves2bfloat162(l2, l3);
}

// ---------------------------------------------------------------------------
// Tensor-core GEMM on pre-split bf16 hi/lo operands.
// EPI 1: gelu(acc+bias)->(Ch,Cl) ; EPI 2: C += acc + bias (fp32) ;
// EPI 3: acc -> (Ch,Cl) bf16 hi/lo (no bias)
// 3-stage cp.async ring, ONE __syncthreads per stage (slot s+2 == slot s-1,
// whose compute finished before this iteration's barrier).
// __launch_bounds__(256, 2): 128 regs, 2 CTAs/SM; smem 3*37888*2 = 227KB/SM.
// ---------------------------------------------------------------------------
#define A_STRIDE 40
#define B_STRIDE 136
#define AH_OFF 0
#define AL_OFF 10240
#define BH_OFF 20480
#define BL_OFF 29184
#define SMEM_STAGE 37888
#define SMEM_BYTES (3*SMEM_STAGE)

template<int EPI>
__global__ void __launch_bounds__(256, 2) tgemm_kernel(
    const __nv_bfloat16* __restrict__ Ahg, const __nv_bfloat16* __restrict__ Alg,
    const __nv_bfloat16* __restrict__ Bhg, const __nv_bfloat16* __restrict__ Blg,
    const float* __restrict__ bias, float* __restrict__ C,
    __nv_bfloat16* __restrict__ Ch, __nv_bfloat16* __restrict__ Cl,
    int M, int N, int K)
{
    extern __shared__ char smem[];
    const u32 sbase = (u32)__cvta_generic_to_shared(smem);

    const int tid  = threadIdx.x;
    const int lane = tid & 31;
    const int wid  = tid >> 5;
    const int wm = wid & 3;
    const int wn = wid >> 2;
    const int bx = blockIdx.x;
    const int by = blockIdx.y;

    float acc[2][8][4];
    #pragma unroll
    for (int i = 0; i < 2; i++)
        #pragma unroll
        for (int j = 0; j < 8; j++)
            #pragma unroll
            for (int q = 0; q < 4; q++) acc[i][j][q] = 0.f;

    const int g  = lane >> 3;
    const int lr = lane & 7;
    const int m0 = wm * 32;
    const int n0 = wn * 64;

    const int a_r0 = tid >> 2,  a_c0 = tid & 3;
    const int b_r0 = tid >> 4,  b_c0 = tid & 15;

    auto load_stage = [&](int slot, int k0) {
        const u32 so = sbase + slot * SMEM_STAGE;
        #pragma unroll
        for (int i = 0; i < 2; i++) {
            int ar = a_r0 + i * 64;
            const size_t asrc = (size_t)(by * 128 + ar) * K + k0 + a_c0 * 8;
            cp16(so + AH_OFF + ar * 80 + a_c0 * 16, Ahg + asrc);
            cp16(so + AL_OFF + ar * 80 + a_c0 * 16, Alg + asrc);
            int br = b_r0 + i * 16;
            const size_t bsrc = (size_t)(k0 + br) * N + bx * 128 + b_c0 * 8;
            cp16(so + BH_OFF + br * 272 + b_c0 * 16, Bhg + bsrc);
            cp16(so + BL_OFF + br * 272 + b_c0 * 16, Blg + bsrc);
        }
    };

    const int nst = K / 32;
    load_stage(0, 0);
    cp_commit();
    if (nst > 1) {
        load_stage(1, 32);
        cp_commit();
    }

    int slot = 0;
    for (int s = 0; s < nst; s++) {
        if (s + 1 < nst) {
            cp_wait<1>();
        } else {
            cp_wait<0>();
        }
        __syncthreads();
        if (s + 2 < nst) {
            int ns = slot + 2;
            if (ns >= 3) ns -= 3;
            load_stage(ns, (s + 2) * 32);
            cp_commit();
        }

        const u32 aH = sbase + slot * SMEM_STAGE + AH_OFF;
        const u32 aL = sbase + slot * SMEM_STAGE + AL_OFF;
        const u32 bH = sbase + slot * SMEM_STAGE + BH_OFF;
        const u32 bL = sbase + slot * SMEM_STAGE + BL_OFF;

        #pragma unroll
        for (int ks = 0; ks < 32; ks += 16) {
            u32 fah[2][4], fal[2][4], fbh[4][4], fbl[4][4];
            #pragma unroll
            for (int mi = 0; mi < 2; mi++) {
                int row = m0 + mi * 16 + lr + (g & 1) * 8;
                int col = ks + (g >> 1) * 8;
                u32 ofs = (u32)(row * A_STRIDE + col) * 2u;
                ldsm_x4(fah[mi], aH + ofs);
                ldsm_x4(fal[mi], aL + ofs);
            }
            #pragma unroll
            for (int pj = 0; pj < 4; pj++) {
                int krow = ks + lr + (g & 1) * 8;
                int ncol = n0 + pj * 16 + (g >> 1) * 8;
                u32 ofs = (u32)(krow * B_STRIDE + ncol) * 2u;
                ldsm_x4t(fbh[pj], bH + ofs);
                ldsm_x4t(fbl[pj], bL + ofs);
            }
            #pragma unroll
            for (int mi = 0; mi < 2; mi++) {
                #pragma unroll
                for (int nj = 0; nj < 8; nj++) {
                    int pj = nj >> 1;
                    int hf = nj & 1;
                    mma_bf16(acc[mi][nj], fah[mi], fbh[pj][hf*2], fbh[pj][hf*2+1]);
                    mma_bf16(acc[mi][nj], fah[mi], fbl[pj][hf*2], fbl[pj][hf*2+1]);
                    mma_bf16(acc[mi][nj], fal[mi], fbh[pj][hf*2], fbh[pj][hf*2+1]);
                }
            }
        }
        if (++slot == 3) slot = 0;
    }

    const int rbase = by * 128 + m0 + (lane >> 2);
    const int cbase = bx * 128 + n0 + (lane & 3) * 2;
    #pragma unroll
    for (int mi = 0; mi < 2; mi++) {
        #pragma unroll
        for (int nj = 0; nj < 8; nj++) {
            int col = cbase + nj * 8;
            float b0 = 0.f, b1 = 0.f;
            if (EPI == 1 || EPI == 2) { b0 = bias[col]; b1 = bias[col + 1]; }
            #pragma unroll
            for (int half = 0; half < 2; half++) {
                size_t r = (size_t)(rbase + mi * 16 + half * 8);
                float v0 = acc[mi][nj][half * 2 + 0];
                float v1 = acc[mi][nj][half * 2 + 1];
                if (EPI == 1) {
                    float g0 = gelu_tanh(v0 + b0);
                    float g1 = gelu_tanh(v1 + b1);
                    __nv_bfloat16 h0 = __float2bfloat16(g0);
                    __nv_bfloat16 h1 = __float2bfloat16(g1);
                    __nv_bfloat16 l0 = __float2bfloat16(g0 - __bfloat162float(h0));
                    __nv_bfloat16 l1 = __float2bfloat16(g1 - __bfloat162float(h1));
                    *(__nv_bfloat162*)(Ch + r * N + col) = __halves2bfloat162(h0, h1);
                    *(__nv_bfloat162*)(Cl + r * N + col) = __halves2bfloat162(l0, l1);
                } else if (EPI == 2) {
                    float* cp = C + r * N + col;
                    float2 c = *(float2*)cp;
                    c.x += v0 + b0;
                    c.y += v1 + b1;
                    *(float2*)cp = c;
                } else {  // EPI == 3
                    __nv_bfloat16 h0 = __float2bfloat16(v0);
                    __nv_bfloat16 h1 = __float2bfloat16(v1);
                    __nv_bfloat16 l0 = __float2bfloat16(v0 - __bfloat162float(h0));
                    __nv_bfloat16 l1 = __float2bfloat16(v1 - __bfloat162float(h1));
                    *(__nv_bfloat162*)(Ch + r * N + col) = __halves2bfloat162(h0, h1);
                    *(__nv_bfloat162*)(Cl + r * N + col) = __halves2bfloat162(l0, l1);
                }
            }
        }
    }
}

// ---------------------------------------------------------------------------
// Tensor-core flash attention, bf16x3. CTA = 4 warps, Br=64, Bc=64.
// grid (T/64, H, B). Q/K/V are bf16 hi/lo, [B, seq, H*HD] layout.
// ---------------------------------------------------------------------------
#define KV_STRIDE 72          // 64 bf16 + 8 pad
#define AT_QH 0
#define AT_QL 9216
#define AT_ST 18432
#define AT_STAGE 36864        // Kh,Kl,Vh,Vl each 9216
#define ATTN_SMEM (AT_ST + 2*AT_STAGE)

template<bool CAUSAL>
__global__ void __launch_bounds__(128) attn_mma_kernel(
    const __nv_bfloat16* __restrict__ Qh, const __nv_bfloat16* __restrict__ Ql,
    const __nv_bfloat16* __restrict__ Kh, const __nv_bfloat16* __restrict__ Kl,
    const __nv_bfloat16* __restrict__ Vh, const __nv_bfloat16* __restrict__ Vl,
    __nv_bfloat16* __restrict__ Oh, __nv_bfloat16* __restrict__ Ol)
{
    extern __shared__ char smem[];
    const u32 sbase = (u32)__cvta_generic_to_shared(smem);

    const int qblk = blockIdx.x;
    const int h    = blockIdx.y;
    const int b    = blockIdx.z;
    const int tid  = threadIdx.x;
    const int lane = tid & 31;
    const int w    = tid >> 5;
    const int g    = lane >> 3;
    const int lr   = lane & 7;

    #pragma unroll
    for (int i = 0; i < 4; i++) {
        int idx = tid + i * 128;
        int r = idx >> 3;
        int c = idx & 7;
        size_t src = ((size_t)b * TT + qblk * 64 + r) * EE + h * HDIM + c * 8;
        *(float4*)(smem + AT_QH + (r * KV_STRIDE + c * 8) * 2) = *(const float4*)(Qh + src);
        *(float4*)(smem + AT_QL + (r * KV_STRIDE + c * 8) * 2) = *(const float4*)(Ql + src);
    }
    __syncthreads();

    u32 qfh[4][4], qfl[4][4];
    #pragma unroll
    for (int kc = 0; kc < 4; kc++) {
        int row = w * 16 + lr + (g & 1) * 8;
        int col = kc * 16 + (g >> 1) * 8;
        u32 ofs = (u32)(row * KV_STRIDE + col) * 2u;
        ldsm_x4(qfh[kc], sbase + AT_QH + ofs);
        ldsm_x4(qfl[kc], sbase + AT_QL + ofs);
    }

    auto load_kv = [&](int stg, int kt) {
        const u32 so = sbase + AT_ST + stg * AT_STAGE;
        #pragma unroll
        for (int i = 0; i < 4; i++) {
            int idx = tid + i * 128;
            int r = idx >> 3;
            int c = idx & 7;
            size_t src = ((size_t)b * SS + kt + r) * EE + h * HDIM + c * 8;
            u32 d = so + (r * KV_STRIDE + c * 8) * 2;
            cp16(d,          Kh + src);
            cp16(d + 9216,   Kl + src);
            cp16(d + 18432,  Vh + src);
            cp16(d + 27648,  Vl + src);
        }
    };

    float oacc[8][4];
    #pragma unroll
    for (int t = 0; t < 8; t++)
        #pragma unroll
        for (int e = 0; e < 4; e++) oacc[t][e] = 0.f;
    float mrow[2] = {-1e30f, -1e30f};
    float lrow[2] = {0.f, 0.f};

    const int nblk = CAUSAL ? (qblk + 1) : (SS / 64);

    load_kv(0, 0);
    cp_commit();

    for (int jb = 0; jb < nblk; jb++) {
        const int buf = jb & 1;
        if (jb + 1 < nblk) {
            load_kv(buf ^ 1, (jb + 1) * 64);
            cp_commit();
            cp_wait<1>();
        } else {
            cp_wait<0>();
        }
        __syncthreads();

        const u32 soKh = sbase + AT_ST + buf * AT_STAGE;
        const u32 soKl = soKh + 9216;
        const u32 soVh = soKh + 18432;
        const u32 soVl = soKh + 27648;

        float sacc[8][4];
        #pragma unroll
        for (int t = 0; t < 8; t++)
            #pragma unroll
            for (int e = 0; e < 4; e++) sacc[t][e] = 0.f;

        #pragma unroll
        for (int kc = 0; kc < 4; kc++) {
            #pragma unroll
            for (int nt2 = 0; nt2 < 4; nt2++) {
                int key = nt2 * 16 + (g >> 1) * 8 + lr;
                int hd  = kc * 16 + (g & 1) * 8;
                u32 ofs = (u32)(key * KV_STRIDE + hd) * 2u;
                u32 kbh[4], kbl[4];
                ldsm_x4(kbh, soKh + ofs);
                ldsm_x4(kbl, soKl + ofs);
                mma_bf16(sacc[nt2*2],   qfh[kc], kbh[0], kbh[1]);
                mma_bf16(sacc[nt2*2],   qfh[kc], kbl[0], kbl[1]);
                mma_bf16(sacc[nt2*2],   qfl[kc], kbh[0], kbh[1]);
                mma_bf16(sacc[nt2*2+1], qfh[kc], kbh[2], kbh[3]);
                mma_bf16(sacc[nt2*2+1], qfh[kc], kbl[2], kbl[3]);
                mma_bf16(sacc[nt2*2+1], qfl[kc], kbh[2], kbh[3]);
            }
        }

        #pragma unroll
        for (int t = 0; t < 8; t++) {
            #pragma unroll
            for (int e = 0; e < 4; e++) {
                float s = sacc[t][e] * 0.125f;
                if (CAUSAL && jb == qblk) {
                    int key = jb * 64 + t * 8 + (lane & 3) * 2 + (e & 1);
                    int qr  = qblk * 64 + w * 16 + (lane >> 2) + (e >> 1) * 8;
                    if (key > qr) s = -1e30f;
                }
                sacc[t][e] = s;
            }
        }

        float mr[2] = {-1e30f, -1e30f};
        #pragma unroll
        for (int t = 0; t < 8; t++) {
            mr[0] = fmaxf(mr[0], fmaxf(sacc[t][0], sacc[t][1]));
            mr[1] = fmaxf(mr[1], fmaxf(sacc[t][2], sacc[t][3]));
        }
        #pragma unroll
        for (int r = 0; r < 2; r++) {
            mr[r] = fmaxf(mr[r], __shfl_xor_sync(0xffffffffu, mr[r], 1));
            mr[r] = fmaxf(mr[r], __shfl_xor_sync(0xffffffffu, mr[r], 2));
        }
        float mnew[2], corr[2], rsum[2];
        #pragma unroll
        for (int r = 0; r < 2; r++) {
            mnew[r] = fmaxf(mrow[r], mr[r]);
            corr[r] = __expf(mrow[r] - mnew[r]);
            rsum[r] = 0.f;
        }
        #pragma unroll
        for (int t = 0; t < 8; t++) {
            float p0 = __expf(sacc[t][0] - mnew[0]);
            float p1 = __expf(sacc[t][1] - mnew[0]);
            float p2 = __expf(sacc[t][2] - mnew[1]);
            float p3 = __expf(sacc[t][3] - mnew[1]);
            sacc[t][0] = p0; sacc[t][1] = p1; sacc[t][2] = p2; sacc[t][3] = p3;
            rsum[0] += p0 + p1;
            rsum[1] += p2 + p3;
        }
        #pragma unroll
        for (int r = 0; r < 2; r++) {
            rsum[r] += __shfl_xor_sync(0xffffffffu, rsum[r], 1);
            rsum[r] += __shfl_xor_sync(0xffffffffu, rsum[r], 2);
            lrow[r] = lrow[r] * corr[r] + rsum[r];
            mrow[r] = mnew[r];
        }
        #pragma unroll
        for (int t = 0; t < 8; t++) {
            oacc[t][0] *= corr[0];
            oacc[t][1] *= corr[0];
            oacc[t][2] *= corr[1];
            oacc[t][3] *= corr[1];
        }

        u32 pfh[4][4], pfl[4][4];
        #pragma unroll
        for (int kc = 0; kc < 4; kc++) {
            #pragma unroll
            for (int j = 0; j < 4; j++) {
                int t = kc * 2 + (j >> 1);
                int e = (j & 1) * 2;
                float p0 = sacc[t][e], p1 = sacc[t][e + 1];
                __nv_bfloat16 h0 = __float2bfloat16(p0);
                __nv_bfloat16 h1 = __float2bfloat16(p1);
                pfh[kc][j] = packbf(p0, p1);
                pfl[kc][j] = packbf(p0 - __bfloat162float(h0), p1 - __bfloat162float(h1));
            }
        }

        #pragma unroll
        for (int kc = 0; kc < 4; kc++) {
            #pragma unroll
            for (int nt2 = 0; nt2 < 4; nt2++) {
                int key = kc * 16 + (g & 1) * 8 + lr;
                int hd  = nt2 * 16 + (g >> 1) * 8;
                u32 ofs = (u32)(key * KV_STRIDE + hd) * 2u;
                u32 vbh[4], vbl[4];
                ldsm_x4t(vbh, soVh + ofs);
                ldsm_x4t(vbl, soVl + ofs);
                mma_bf16(oacc[nt2*2],   pfh[kc], vbh[0], vbh[1]);
                mma_bf16(oacc[nt2*2],   pfh[kc], vbl[0], vbl[1]);
                mma_bf16(oacc[nt2*2],   pfl[kc], vbh[0], vbh[1]);
                mma_bf16(oacc[nt2*2+1], pfh[kc], vbh[2], vbh[3]);
                mma_bf16(oacc[nt2*2+1], pfh[kc], vbl[2], vbl[3]);
                mma_bf16(oacc[nt2*2+1], pfl[kc], vbh[2], vbh[3]);
            }
        }
        __syncthreads();
    }

    float inv0 = 1.f / lrow[0];
    float inv1 = 1.f / lrow[1];
    size_t row0 = (size_t)b * TT + qblk * 64 + w * 16 + (lane >> 2);
    size_t row1 = row0 + 8;
    #pragma unroll
    for (int nt = 0; nt < 8; nt++) {
        int col = h * HDIM + nt * 8 + (lane & 3) * 2;
        float a0 = oacc[nt][0] * inv0;
        float a1 = oacc[nt][1] * inv0;
        float c0 = oacc[nt][2] * inv1;
        float c1 = oacc[nt][3] * inv1;
        __nv_bfloat16 ah0 = __float2bfloat16(a0);
        __nv_bfloat16 ah1 = __float2bfloat16(a1);
        __nv_bfloat16 ch0 = __float2bfloat16(c0);
        __nv_bfloat16 ch1 = __float2bfloat16(c1);
        *(u32*)(Oh + row0 * EE + col) = packbf(a0, a1);
        *(u32*)(Ol + row0 * EE + col) = packbf(a0 - __bfloat162float(ah0), a1 - __bfloat162float(ah1));
        *(u32*)(Oh + row1 * EE + col) = packbf(c0, c1);
        *(u32*)(Ol + row1 * EE + col) = packbf(c0 - __bfloat162float(ch0), c1 - __bfloat162float(ch1));
    }
}

// ---------------------------------------------------------------------------
// Launch helpers
// ---------------------------------------------------------------------------
static void run_gemm(int epi,
                     const __nv_bfloat16* Ah, const __nv_bfloat16* Al,
                     const __nv_bfloat16* Bh, const __nv_bfloat16* Bl,
                     const float* bias, float* C,
                     __nv_bfloat16* Ch, __nv_bfloat16* Cl,
                     int M, int N, int K)
{
    dim3 grid(N / 128, M / 128);
    if (epi == 1) {
        cudaFuncSetAttribute(tgemm_kernel<1>, cudaFuncAttributeMaxDynamicSharedMemorySize, SMEM_BYTES);
        tgemm_kernel<1><<<grid, 256, SMEM_BYTES>>>(Ah, Al, Bh, Bl, bias, C, Ch, Cl, M, N, K);
    } else if (epi == 2) {
        cudaFuncSetAttribute(tgemm_kernel<2>, cudaFuncAttributeMaxDynamicSharedMemorySize, SMEM_BYTES);
        tgemm_kernel<2><<<grid, 256, SMEM_BYTES>>>(Ah, Al, Bh, Bl, bias, C, Ch, Cl, M, N, K);
    } else {
        cudaFuncSetAttribute(tgemm_kernel<3>, cudaFuncAttributeMaxDynamicSharedMemorySize, SMEM_BYTES);
        tgemm_kernel<3><<<grid, 256, SMEM_BYTES>>>(Ah, Al, Bh, Bl, bias, C, Ch, Cl, M, N, K);
    }
}

static void run_split(const float* in, __nv_bfloat16* hi, __nv_bfloat16* lo, size_t n)
{
    split_kernel<<<(unsigned)(n / 1024), 256>>>(in, hi, lo);
}

static void run_attn(bool causal,
                     const __nv_bfloat16* qh, const __nv_bfloat16* ql,
                     const __nv_bfloat16* kh, const __nv_bfloat16* kl,
                     const __nv_bfloat16* vh, const __nv_bfloat16* vl,
                     __nv_bfloat16* oh, __nv_bfloat16* ol)
{
    dim3 grid(TT / 64, HH, BB);
    if (causal) {
        cudaFuncSetAttribute(attn_mma_kernel<true>, cudaFuncAttributeMaxDynamicSharedMemorySize, ATTN_SMEM);
        attn_mma_kernel<true><<<grid, 128, ATTN_SMEM>>>(qh, ql, kh, kl, vh, vl, oh, ol);
    } else {
        cudaFuncSetAttribute(attn_mma_kernel<false>, cudaFuncAttributeMaxDynamicSharedMemorySize, ATTN_SMEM);
        attn_mma_kernel<false><<<grid, 128, ATTN_SMEM>>>(qh, ql, kh, kl, vh, vl, oh, ol);
    }
}

extern "C" void kernel_launch(void* const* d_in, const int* in_sizes, int n_in,
                              void* d_out, int out_size)
{
    const float* enc   = (const float*)d_in[0];
    const float* dec   = (const float*)d_in[1];
    const float* ln1_w = (const float*)d_in[2];
    const float* ln1_b = (const float*)d_in[3];
    const float* ln2_w = (const float*)d_in[4];
    const float* ln2_b = (const float*)d_in[5];
    const float* ln3_w = (const float*)d_in[6];
    const float* ln3_b = (const float*)d_in[7];
    const float* Wq_s  = (const float*)d_in[8];
    const float* Wk_s  = (const float*)d_in[9];
    const float* Wv_s  = (const float*)d_in[10];
    const float* Wo_s  = (const float*)d_in[11];
    const float* bo_s  = (const float*)d_in[12];
    const float* Wq_c  = (const float*)d_in[13];
    const float* Wk_c  = (const float*)d_in[14];
    const float* Wv_c  = (const float*)d_in[15];
    const float* Wo_c  = (const float*)d_in[16];
    const float* bo_c  = (const float*)d_in[17];
    const float* W1    = (const float*)d_in[18];
    const float* b1p   = (const float*)d_in[19];
    const float* W2    = (const float*)d_in[20];
    const float* b2p   = (const float*)d_in[21];

    __nv_bfloat16 *qh, *ql, *kh, *kl, *vh, *vl;
    __nv_bfloat16 *nxh, *nxl, *ench, *encl, *ath, *atl, *ffh, *ffl, *wh, *wl;
    cudaGetSymbolAddress((void**)&qh,   g_qh);
    cudaGetSymbolAddress((void**)&ql,   g_ql);
    cudaGetSymbolAddress((void**)&kh,   g_kh);
    cudaGetSymbolAddress((void**)&kl,   g_kl);
    cudaGetSymbolAddress((void**)&vh,   g_vh);
    cudaGetSymbolAddress((void**)&vl,   g_vl);
    cudaGetSymbolAddress((void**)&nxh,  g_nxh);
    cudaGetSymbolAddress((void**)&nxl,  g_nxl);
    cudaGetSymbolAddress((void**)&ench, g_ench);
    cudaGetSymbolAddress((void**)&encl, g_encl);
    cudaGetSymbolAddress((void**)&ath,  g_ath);
    cudaGetSymbolAddress((void**)&atl,  g_atl);
    cudaGetSymbolAddress((void**)&ffh,  g_ffh);
    cudaGetSymbolAddress((void**)&ffl,  g_ffl);
    cudaGetSymbolAddress((void**)&wh,   g_wh);
    cudaGetSymbolAddress((void**)&wl,   g_wl);

    float* x = (float*)d_out;

    cudaMemcpyAsync(x, dec, (size_t)MROWS * EE * sizeof(float),
                    cudaMemcpyDeviceToDevice);

    run_split(enc, ench, encl, (size_t)MROWS * EE);

    for (int l = 0; l < LNUM; l++) {
        const size_t wE  = (size_t)l * EE * EE;
        const size_t wF1 = (size_t)l * EE * FF;
        const size_t wF2 = (size_t)l * FF * EE;

        // ---- self attention ----
        layernorm_kernel<<<MROWS, 256>>>(x, ln1_w + l * EE, ln1_b + l * EE, nxh, nxl);
        run_split(Wq_s + wE, wh, wl, (size_t)EE * EE);
        run_gemm(3, nxh, nxl, wh, wl, 0, 0, qh, ql, MROWS, EE, EE);
        run_split(Wk_s + wE, wh, wl, (size_t)EE * EE);
        run_gemm(3, nxh, nxl, wh, wl, 0, 0, kh, kl, MROWS, EE, EE);
        run_split(Wv_s + wE, wh, wl, (size_t)EE * EE);
        run_gemm(3, nxh, nxl, wh, wl, 0, 0, vh, vl, MROWS, EE, EE);
        run_attn(true, qh, ql, kh, kl, vh, vl, ath, atl);
        run_split(Wo_s + wE, wh, wl, (size_t)EE * EE);
        run_gemm(2, ath, atl, wh, wl, bo_s + l * EE, x, 0, 0, MROWS, EE, EE);

        // ---- cross attention ----
        layernorm_kernel<<<MROWS, 256>>>(x, ln2_w + l * EE, ln2_b + l * EE, nxh, nxl);
        run_split(Wq_c + wE, wh, wl, (size_t)EE * EE);
        run_gemm(3, nxh, nxl, wh, wl, 0, 0, qh, ql, MROWS, EE, EE);
        run_split(Wk_c + wE, wh, wl, (size_t)EE * EE);
        run_gemm(3, ench, encl, wh, wl, 0, 0, kh, kl, MROWS, EE, EE);
        run_split(Wv_c + wE, wh, wl, (size_t)EE * EE);
        run_gemm(3, ench, encl, wh, wl, 0, 0, vh, vl, MROWS, EE, EE);
        run_attn(false, qh, ql, kh, kl, vh, vl, ath, atl);
        run_split(Wo_c + wE, wh, wl, (size_t)EE * EE);
        run_gemm(2, ath, atl, wh, wl, bo_c + l * EE, x, 0, 0, MROWS, EE, EE);

        // ---- FFN ----
        layernorm_kernel<<<MROWS, 256>>>(x, ln3_w + l * EE, ln3_b + l * EE, nxh, nxl);
        run_split(W1 + wF1, wh, wl, (size_t)EE * FF);
        run_gemm(1, nxh, nxl, wh, wl, b1p + (size_t)l * FF, 0, ffh, ffl, MROWS, FF, EE);
        run_split(W2 + wF2, wh, wl, (size_t)FF * EE);
        run_gemm(2, ffh, ffl, wh, wl, b2p + (size_t)l * EE, x, 0, 0, MROWS, EE, FF);
    }
}

// round 17
// speedup vs baseline: 1.0278x; 1.0278x over previous
#include <cuda_runtime.h>
#include <cuda_bf16.h>
#include <cstdint>
#include <math.h>

typedef unsigned int u32;

// Problem constants
#define LNUM 6
#define BB   8
#define TT   1024
#define SS   1024
#define EE   1024
#define HH   16
#define HDIM 64
#define FF   4096
#define MROWS (BB*TT)
#define LN_EPS 1e-5f

// ---------------------------------------------------------------------------
// Scratch (device globals; no allocation allowed)
// ---------------------------------------------------------------------------
__device__ __nv_bfloat16 g_qh  [(size_t)MROWS*EE];
__device__ __nv_bfloat16 g_ql  [(size_t)MROWS*EE];
__device__ __nv_bfloat16 g_kh  [(size_t)MROWS*EE];
__device__ __nv_bfloat16 g_kl  [(size_t)MROWS*EE];
__device__ __nv_bfloat16 g_vh  [(size_t)MROWS*EE];
__device__ __nv_bfloat16 g_vl  [(size_t)MROWS*EE];
__device__ __nv_bfloat16 g_nxh [(size_t)MROWS*EE];
__device__ __nv_bfloat16 g_nxl [(size_t)MROWS*EE];
__device__ __nv_bfloat16 g_ench[(size_t)MROWS*EE];
__device__ __nv_bfloat16 g_encl[(size_t)MROWS*EE];
__device__ __nv_bfloat16 g_ath [(size_t)MROWS*EE];
__device__ __nv_bfloat16 g_atl [(size_t)MROWS*EE];
__device__ __nv_bfloat16 g_ffh [(size_t)MROWS*FF];
__device__ __nv_bfloat16 g_ffl [(size_t)MROWS*FF];
__device__ __nv_bfloat16 g_wh  [(size_t)EE*FF];
__device__ __nv_bfloat16 g_wl  [(size_t)EE*FF];

// ---------------------------------------------------------------------------
// Common device helpers
// ---------------------------------------------------------------------------
__device__ __forceinline__ float gelu_tanh(float x) {
    float x3 = x * x * x;
    return 0.5f * x * (1.f + tanhf(0.79788456080286535588f * (x + 0.044715f * x3)));
}
__device__ __forceinline__ void ldsm_x4(u32* r, u32 a) {
    asm volatile("ldmatrix.sync.aligned.m8n8.x4.shared.b16 {%0,%1,%2,%3}, [%4];"
                 : "=r"(r[0]), "=r"(r[1]), "=r"(r[2]), "=r"(r[3]) : "r"(a));
}
__device__ __forceinline__ void ldsm_x4t(u32* r, u32 a) {
    asm volatile("ldmatrix.sync.aligned.m8n8.x4.trans.shared.b16 {%0,%1,%2,%3}, [%4];"
                 : "=r"(r[0]), "=r"(r[1]), "=r"(r[2]), "=r"(r[3]) : "r"(a));
}
__device__ __forceinline__ void mma_bf16(float* c, const u32* a, u32 b0, u32 b1) {
    asm volatile(
        "mma.sync.aligned.m16n8k16.row.col.f32.bf16.bf16.f32 "
        "{%0,%1,%2,%3}, {%4,%5,%6,%7}, {%8,%9}, {%0,%1,%2,%3};"
        : "+f"(c[0]), "+f"(c[1]), "+f"(c[2]), "+f"(c[3])
        : "r"(a[0]), "r"(a[1]), "r"(a[2]), "r"(a[3]), "r"(b0), "r"(b1));
}
__device__ __forceinline__ void cp16(u32 dst, const void* src) {
    asm volatile("cp.async.cg.shared.global [%0], [%1], 16;\n" :: "r"(dst), "l"(src));
}
__device__ __forceinline__ void cp_commit() {
    asm volatile("cp.async.commit_group;\n");
}
template<int N>
__device__ __forceinline__ void cp_wait() {
    asm volatile("cp.async.wait_group %0;\n" :: "n"(N));
}
__device__ __forceinline__ u32 packbf(float x, float y) {
    __nv_bfloat162 t = __halves2bfloat162(__float2bfloat16(x), __float2bfloat16(y));
    return *(u32*)&t;
}

// ---------------------------------------------------------------------------
// Elementwise fp32 -> bf16 (hi, lo) splitter. n multiple of 1024.
// ---------------------------------------------------------------------------
__global__ void __launch_bounds__(256) split_kernel(
    const float* __restrict__ in,
    __nv_bfloat16* __restrict__ hi, __nv_bfloat16* __restrict__ lo)
{
    size_t i = ((size_t)blockIdx.x * 256 + threadIdx.x) * 4;
    float4 v = *(const float4*)(in + i);
    __nv_bfloat16 h0 = __float2bfloat16(v.x);
    __nv_bfloat16 h1 = __float2bfloat16(v.y);
    __nv_bfloat16 h2 = __float2bfloat16(v.z);
    __nv_bfloat16 h3 = __float2bfloat16(v.w);
    __nv_bfloat16 l0 = __float2bfloat16(v.x - __bfloat162float(h0));
    __nv_bfloat16 l1 = __float2bfloat16(v.y - __bfloat162float(h1));
    __nv_bfloat16 l2 = __float2bfloat16(v.z - __bfloat162float(h2));
    __nv_bfloat16 l3 = __float2bfloat16(v.w - __bfloat162float(h3));
    *(__nv_bfloat162*)(hi + i)     = __halves2bfloat162(h0, h1);
    *(__nv_bfloat162*)(hi + i + 2) = __halves2bfloat162(h2, h3);
    *(__nv_bfloat162*)(lo + i)     = __halves2bfloat162(l0, l1);
    *(__nv_bfloat162*)(lo + i + 2) = __halves2bfloat162(l2, l3);
}

// ---------------------------------------------------------------------------
// LayerNorm -> bf16 hi/lo outputs
// ---------------------------------------------------------------------------
__global__ void __launch_bounds__(256) layernorm_kernel(
    const float* __restrict__ x, const float* __restrict__ w,
    const float* __restrict__ b,
    __nv_bfloat16* __restrict__ oh, __nv_bfloat16* __restrict__ ol)
{
    const int row = blockIdx.x;
    const int tid = threadIdx.x;
    const float4* xr = (const float4*)(x + (size_t)row * EE);
    float4 xv = xr[tid];
    float s  = xv.x + xv.y + xv.z + xv.w;
    float sq = xv.x*xv.x + xv.y*xv.y + xv.z*xv.z + xv.w*xv.w;
    #pragma unroll
    for (int o = 16; o > 0; o >>= 1) {
        s  += __shfl_down_sync(0xffffffffu, s,  o);
        sq += __shfl_down_sync(0xffffffffu, sq, o);
    }
    __shared__ float ss[8];
    __shared__ float ssq[8];
    __shared__ float mean_s, rstd_s;
    const int wid = tid >> 5;
    const int lane = tid & 31;
    if (lane == 0) { ss[wid] = s; ssq[wid] = sq; }
    __syncthreads();
    if (tid == 0) {
        float ts = 0.f, tq = 0.f;
        #pragma unroll
        for (int i = 0; i < 8; i++) { ts += ss[i]; tq += ssq[i]; }
        float m   = ts * (1.f / EE);
        float var = tq * (1.f / EE) - m * m;
        mean_s = m;
        rstd_s = rsqrtf(var + LN_EPS);
    }
    __syncthreads();
    const float m = mean_s;
    const float r = rstd_s;
    float4 wv = ((const float4*)w)[tid];
    float4 bv = ((const float4*)b)[tid];
    float o0 = (xv.x - m) * r * wv.x + bv.x;
    float o1 = (xv.y - m) * r * wv.y + bv.y;
    float o2 = (xv.z - m) * r * wv.z + bv.z;
    float o3 = (xv.w - m) * r * wv.w + bv.w;
    __nv_bfloat16 h0 = __float2bfloat16(o0);
    __nv_bfloat16 h1 = __float2bfloat16(o1);
    __nv_bfloat16 h2 = __float2bfloat16(o2);
    __nv_bfloat16 h3 = __float2bfloat16(o3);
    __nv_bfloat16 l0 = __float2bfloat16(o0 - __bfloat162float(h0));
    __nv_bfloat16 l1 = __float2bfloat16(o1 - __bfloat162float(h1));
    __nv_bfloat16 l2 = __float2bfloat16(o2 - __bfloat162float(h2));
    __nv_bfloat16 l3 = __float2bfloat16(o3 - __bfloat162float(h3));
    size_t o = (size_t)row * EE + tid * 4;
    *(__nv_bfloat162*)(oh + o)     = __halves2bfloat162(h0, h1);
    *(__nv_bfloat162*)(oh + o + 2) = __halves2bfloat162(h2, h3);
    *(__nv_bfloat162*)(ol + o)     = __halves2bfloat162(l0, l1);
    *(__nv_bfloat162*)(ol + o + 2) = __halves2bfloat162(l2, l3);
}

// ---------------------------------------------------------------------------
// Tensor-core GEMM on pre-split bf16 hi/lo operands.
// EPI 1: gelu(acc+bias)->(Ch,Cl) ; EPI 2: C += acc + bias (fp32) ;
// EPI 3: acc -> (Ch,Cl) bf16 hi/lo (no bias)
// 2-stage cp.async. Inner loop streams B fragments per pj (2 LDSM : 12 MMA)
// with pass-major MMA order to break accumulator RAW chains.
// ---------------------------------------------------------------------------
#define A_STRIDE 40
#define B_STRIDE 136
#define AH_OFF 0
#define AL_OFF 10240
#define BH_OFF 20480
#define BL_OFF 29184
#define SMEM_STAGE 37888
#define SMEM_BYTES (2*SMEM_STAGE)

template<int EPI>
__global__ void __launch_bounds__(256, 2) tgemm_kernel(
    const __nv_bfloat16* __restrict__ Ahg, const __nv_bfloat16* __restrict__ Alg,
    const __nv_bfloat16* __restrict__ Bhg, const __nv_bfloat16* __restrict__ Blg,
    const float* __restrict__ bias, float* __restrict__ C,
    __nv_bfloat16* __restrict__ Ch, __nv_bfloat16* __restrict__ Cl,
    int M, int N, int K)
{
    extern __shared__ char smem[];
    const u32 sbase = (u32)__cvta_generic_to_shared(smem);

    const int tid  = threadIdx.x;
    const int lane = tid & 31;
    const int wid  = tid >> 5;
    const int wm = wid & 3;
    const int wn = wid >> 2;
    const int bx = blockIdx.x;
    const int by = blockIdx.y;

    float acc[2][8][4];
    #pragma unroll
    for (int i = 0; i < 2; i++)
        #pragma unroll
        for (int j = 0; j < 8; j++)
            #pragma unroll
            for (int q = 0; q < 4; q++) acc[i][j][q] = 0.f;

    const int g  = lane >> 3;
    const int lr = lane & 7;
    const int m0 = wm * 32;
    const int n0 = wn * 64;

    const int a_r0 = tid >> 2,  a_c0 = tid & 3;
    const int b_r0 = tid >> 4,  b_c0 = tid & 15;

    auto load_stage = [&](int stg, int k0) {
        const u32 so = sbase + stg * SMEM_STAGE;
        #pragma unroll
        for (int i = 0; i < 2; i++) {
            int ar = a_r0 + i * 64;
            const size_t asrc = (size_t)(by * 128 + ar) * K + k0 + a_c0 * 8;
            cp16(so + AH_OFF + ar * 80 + a_c0 * 16, Ahg + asrc);
            cp16(so + AL_OFF + ar * 80 + a_c0 * 16, Alg + asrc);
            int br = b_r0 + i * 16;
            const size_t bsrc = (size_t)(k0 + br) * N + bx * 128 + b_c0 * 8;
            cp16(so + BH_OFF + br * 272 + b_c0 * 16, Bhg + bsrc);
            cp16(so + BL_OFF + br * 272 + b_c0 * 16, Blg + bsrc);
        }
    };

    load_stage(0, 0);
    cp_commit();

    int buf = 0;
    for (int k0 = 0; k0 < K; k0 += 32) {
        if (k0 + 32 < K) {
            load_stage(buf ^ 1, k0 + 32);
            cp_commit();
            cp_wait<1>();
        } else {
            cp_wait<0>();
        }
        __syncthreads();

        const u32 aH = sbase + buf * SMEM_STAGE + AH_OFF;
        const u32 aL = sbase + buf * SMEM_STAGE + AL_OFF;
        const u32 bH = sbase + buf * SMEM_STAGE + BH_OFF;
        const u32 bL = sbase + buf * SMEM_STAGE + BL_OFF;

        #pragma unroll
        for (int ks = 0; ks < 32; ks += 16) {
            u32 fah[2][4], fal[2][4];
            #pragma unroll
            for (int mi = 0; mi < 2; mi++) {
                int row = m0 + mi * 16 + lr + (g & 1) * 8;
                int col = ks + (g >> 1) * 8;
                u32 ofs = (u32)(row * A_STRIDE + col) * 2u;
                ldsm_x4(fah[mi], aH + ofs);
                ldsm_x4(fal[mi], aL + ofs);
            }
            // Stream B fragments one pj at a time: 2 LDSM feed 12 MMA,
            // pass-major so same-accumulator MMAs are 4 apart.
            #pragma unroll
            for (int pj = 0; pj < 4; pj++) {
                int krow = ks + lr + (g & 1) * 8;
                int ncol = n0 + pj * 16 + (g >> 1) * 8;
                u32 ofs = (u32)(krow * B_STRIDE + ncol) * 2u;
                u32 fbh[4], fbl[4];
                ldsm_x4t(fbh, bH + ofs);
                ldsm_x4t(fbl, bL + ofs);
                #pragma unroll
                for (int mi = 0; mi < 2; mi++) {
                    mma_bf16(acc[mi][pj*2],   fah[mi], fbh[0], fbh[1]);
                    mma_bf16(acc[mi][pj*2+1], fah[mi], fbh[2], fbh[3]);
                }
                #pragma unroll
                for (int mi = 0; mi < 2; mi++) {
                    mma_bf16(acc[mi][pj*2],   fah[mi], fbl[0], fbl[1]);
                    mma_bf16(acc[mi][pj*2+1], fah[mi], fbl[2], fbl[3]);
                }
                #pragma unroll
                for (int mi = 0; mi < 2; mi++) {
                    mma_bf16(acc[mi][pj*2],   fal[mi], fbh[0], fbh[1]);
                    mma_bf16(acc[mi][pj*2+1], fal[mi], fbh[2], fbh[3]);
                }
            }
        }
        __syncthreads();
        buf ^= 1;
    }

    const int rbase = by * 128 + m0 + (lane >> 2);
    const int cbase = bx * 128 + n0 + (lane & 3) * 2;
    #pragma unroll
    for (int mi = 0; mi < 2; mi++) {
        #pragma unroll
        for (int nj = 0; nj < 8; nj++) {
            int col = cbase + nj * 8;
            float b0 = 0.f, b1 = 0.f;
            if (EPI == 1 || EPI == 2) { b0 = bias[col]; b1 = bias[col + 1]; }
            #pragma unroll
            for (int half = 0; half < 2; half++) {
                size_t r = (size_t)(rbase + mi * 16 + half * 8);
                float v0 = acc[mi][nj][half * 2 + 0];
                float v1 = acc[mi][nj][half * 2 + 1];
                if (EPI == 1) {
                    float g0 = gelu_tanh(v0 + b0);
                    float g1 = gelu_tanh(v1 + b1);
                    __nv_bfloat16 h0 = __float2bfloat16(g0);
                    __nv_bfloat16 h1 = __float2bfloat16(g1);
                    __nv_bfloat16 l0 = __float2bfloat16(g0 - __bfloat162float(h0));
                    __nv_bfloat16 l1 = __float2bfloat16(g1 - __bfloat162float(h1));
                    *(__nv_bfloat162*)(Ch + r * N + col) = __halves2bfloat162(h0, h1);
                    *(__nv_bfloat162*)(Cl + r * N + col) = __halves2bfloat162(l0, l1);
                } else if (EPI == 2) {
                    float* cp = C + r * N + col;
                    float2 c = *(float2*)cp;
                    c.x += v0 + b0;
                    c.y += v1 + b1;
                    *(float2*)cp = c;
                } else {  // EPI == 3
                    __nv_bfloat16 h0 = __float2bfloat16(v0);
                    __nv_bfloat16 h1 = __float2bfloat16(v1);
                    __nv_bfloat16 l0 = __float2bfloat16(v0 - __bfloat162float(h0));
                    __nv_bfloat16 l1 = __float2bfloat16(v1 - __bfloat162float(h1));
                    *(__nv_bfloat162*)(Ch + r * N + col) = __halves2bfloat162(h0, h1);
                    *(__nv_bfloat162*)(Cl + r * N + col) = __halves2bfloat162(l0, l1);
                }
            }
        }
    }
}

// ---------------------------------------------------------------------------
// Tensor-core flash attention, bf16x3. CTA = 4 warps, Br=64, Bc=64.
// grid (T/64, H, B). Q/K/V are bf16 hi/lo, [B, seq, H*HD] layout.
// ---------------------------------------------------------------------------
#define KV_STRIDE 72          // 64 bf16 + 8 pad
#define AT_QH 0
#define AT_QL 9216
#define AT_ST 18432
#define AT_STAGE 36864        // Kh,Kl,Vh,Vl each 9216
#define ATTN_SMEM (AT_ST + 2*AT_STAGE)

template<bool CAUSAL>
__global__ void __launch_bounds__(128) attn_mma_kernel(
    const __nv_bfloat16* __restrict__ Qh, const __nv_bfloat16* __restrict__ Ql,
    const __nv_bfloat16* __restrict__ Kh, const __nv_bfloat16* __restrict__ Kl,
    const __nv_bfloat16* __restrict__ Vh, const __nv_bfloat16* __restrict__ Vl,
    __nv_bfloat16* __restrict__ Oh, __nv_bfloat16* __restrict__ Ol)
{
    extern __shared__ char smem[];
    const u32 sbase = (u32)__cvta_generic_to_shared(smem);

    const int qblk = blockIdx.x;
    const int h    = blockIdx.y;
    const int b    = blockIdx.z;
    const int tid  = threadIdx.x;
    const int lane = tid & 31;
    const int w    = tid >> 5;
    const int g    = lane >> 3;
    const int lr   = lane & 7;

    #pragma unroll
    for (int i = 0; i < 4; i++) {
        int idx = tid + i * 128;
        int r = idx >> 3;
        int c = idx & 7;
        size_t src = ((size_t)b * TT + qblk * 64 + r) * EE + h * HDIM + c * 8;
        *(float4*)(smem + AT_QH + (r * KV_STRIDE + c * 8) * 2) = *(const float4*)(Qh + src);
        *(float4*)(smem + AT_QL + (r * KV_STRIDE + c * 8) * 2) = *(const float4*)(Ql + src);
    }
    __syncthreads();

    u32 qfh[4][4], qfl[4][4];
    #pragma unroll
    for (int kc = 0; kc < 4; kc++) {
        int row = w * 16 + lr + (g & 1) * 8;
        int col = kc * 16 + (g >> 1) * 8;
        u32 ofs = (u32)(row * KV_STRIDE + col) * 2u;
        ldsm_x4(qfh[kc], sbase + AT_QH + ofs);
        ldsm_x4(qfl[kc], sbase + AT_QL + ofs);
    }

    auto load_kv = [&](int stg, int kt) {
        const u32 so = sbase + AT_ST + stg * AT_STAGE;
        #pragma unroll
        for (int i = 0; i < 4; i++) {
            int idx = tid + i * 128;
            int r = idx >> 3;
            int c = idx & 7;
            size_t src = ((size_t)b * SS + kt + r) * EE + h * HDIM + c * 8;
            u32 d = so + (r * KV_STRIDE + c * 8) * 2;
            cp16(d,          Kh + src);
            cp16(d + 9216,   Kl + src);
            cp16(d + 18432,  Vh + src);
            cp16(d + 27648,  Vl + src);
        }
    };

    float oacc[8][4];
    #pragma unroll
    for (int t = 0; t < 8; t++)
        #pragma unroll
        for (int e = 0; e < 4; e++) oacc[t][e] = 0.f;
    float mrow[2] = {-1e30f, -1e30f};
    float lrow[2] = {0.f, 0.f};

    const int nblk = CAUSAL ? (qblk + 1) : (SS / 64);

    load_kv(0, 0);
    cp_commit();

    for (int jb = 0; jb < nblk; jb++) {
        const int buf = jb & 1;
        if (jb + 1 < nblk) {
            load_kv(buf ^ 1, (jb + 1) * 64);
            cp_commit();
            cp_wait<1>();
        } else {
            cp_wait<0>();
        }
        __syncthreads();

        const u32 soKh = sbase + AT_ST + buf * AT_STAGE;
        const u32 soKl = soKh + 9216;
        const u32 soVh = soKh + 18432;
        const u32 soVl = soKh + 27648;

        float sacc[8][4];
        #pragma unroll
        for (int t = 0; t < 8; t++)
            #pragma unroll
            for (int e = 0; e < 4; e++) sacc[t][e] = 0.f;

        #pragma unroll
        for (int kc = 0; kc < 4; kc++) {
            #pragma unroll
            for (int nt2 = 0; nt2 < 4; nt2++) {
                int key = nt2 * 16 + (g >> 1) * 8 + lr;
                int hd  = kc * 16 + (g & 1) * 8;
                u32 ofs = (u32)(key * KV_STRIDE + hd) * 2u;
                u32 kbh[4], kbl[4];
                ldsm_x4(kbh, soKh + ofs);
                ldsm_x4(kbl, soKl + ofs);
                mma_bf16(sacc[nt2*2],   qfh[kc], kbh[0], kbh[1]);
                mma_bf16(sacc[nt2*2],   qfh[kc], kbl[0], kbl[1]);
                mma_bf16(sacc[nt2*2],   qfl[kc], kbh[0], kbh[1]);
                mma_bf16(sacc[nt2*2+1], qfh[kc], kbh[2], kbh[3]);
                mma_bf16(sacc[nt2*2+1], qfh[kc], kbl[2], kbl[3]);
                mma_bf16(sacc[nt2*2+1], qfl[kc], kbh[2], kbh[3]);
            }
        }

        #pragma unroll
        for (int t = 0; t < 8; t++) {
            #pragma unroll
            for (int e = 0; e < 4; e++) {
                float s = sacc[t][e] * 0.125f;
                if (CAUSAL && jb == qblk) {
                    int key = jb * 64 + t * 8 + (lane & 3) * 2 + (e & 1);
                    int qr  = qblk * 64 + w * 16 + (lane >> 2) + (e >> 1) * 8;
                    if (key > qr) s = -1e30f;
                }
                sacc[t][e] = s;
            }
        }

        float mr[2] = {-1e30f, -1e30f};
        #pragma unroll
        for (int t = 0; t < 8; t++) {
            mr[0] = fmaxf(mr[0], fmaxf(sacc[t][0], sacc[t][1]));
            mr[1] = fmaxf(mr[1], fmaxf(sacc[t][2], sacc[t][3]));
        }
        #pragma unroll
        for (int r = 0; r < 2; r++) {
            mr[r] = fmaxf(mr[r], __shfl_xor_sync(0xffffffffu, mr[r], 1));
            mr[r] = fmaxf(mr[r], __shfl_xor_sync(0xffffffffu, mr[r], 2));
        }
        float mnew[2], corr[2], rsum[2];
        #pragma unroll
        for (int r = 0; r < 2; r++) {
            mnew[r] = fmaxf(mrow[r], mr[r]);
            corr[r] = __expf(mrow[r] - mnew[r]);
            rsum[r] = 0.f;
        }
        #pragma unroll
        for (int t = 0; t < 8; t++) {
            float p0 = __expf(sacc[t][0] - mnew[0]);
            float p1 = __expf(sacc[t][1] - mnew[0]);
            float p2 = __expf(sacc[t][2] - mnew[1]);
            float p3 = __expf(sacc[t][3] - mnew[1]);
            sacc[t][0] = p0; sacc[t][1] = p1; sacc[t][2] = p2; sacc[t][3] = p3;
            rsum[0] += p0 + p1;
            rsum[1] += p2 + p3;
        }
        #pragma unroll
        for (int r = 0; r < 2; r++) {
            rsum[r] += __shfl_xor_sync(0xffffffffu, rsum[r], 1);
            rsum[r] += __shfl_xor_sync(0xffffffffu, rsum[r], 2);
            lrow[r] = lrow[r] * corr[r] + rsum[r];
            mrow[r] = mnew[r];
        }
        #pragma unroll
        for (int t = 0; t < 8; t++) {
            oacc[t][0] *= corr[0];
            oacc[t][1] *= corr[0];
            oacc[t][2] *= corr[1];
            oacc[t][3] *= corr[1];
        }

        u32 pfh[4][4], pfl[4][4];
        #pragma unroll
        for (int kc = 0; kc < 4; kc++) {
            #pragma unroll
            for (int j = 0; j < 4; j++) {
                int t = kc * 2 + (j >> 1);
                int e = (j & 1) * 2;
                float p0 = sacc[t][e], p1 = sacc[t][e + 1];
                __nv_bfloat16 h0 = __float2bfloat16(p0);
                __nv_bfloat16 h1 = __float2bfloat16(p1);
                pfh[kc][j] = packbf(p0, p1);
                pfl[kc][j] = packbf(p0 - __bfloat162float(h0), p1 - __bfloat162float(h1));
            }
        }

        #pragma unroll
        for (int kc = 0; kc < 4; kc++) {
            #pragma unroll
            for (int nt2 = 0; nt2 < 4; nt2++) {
                int key = kc * 16 + (g & 1) * 8 + lr;
                int hd  = nt2 * 16 + (g >> 1) * 8;
                u32 ofs = (u32)(key * KV_STRIDE + hd) * 2u;
                u32 vbh[4], vbl[4];
                ldsm_x4t(vbh, soVh + ofs);
                ldsm_x4t(vbl, soVl + ofs);
                mma_bf16(oacc[nt2*2],   pfh[kc], vbh[0], vbh[1]);
                mma_bf16(oacc[nt2*2],   pfh[kc], vbl[0], vbl[1]);
                mma_bf16(oacc[nt2*2],   pfl[kc], vbh[0], vbh[1]);
                mma_bf16(oacc[nt2*2+1], pfh[kc], vbh[2], vbh[3]);
                mma_bf16(oacc[nt2*2+1], pfh[kc], vbl[2], vbl[3]);
                mma_bf16(oacc[nt2*2+1], pfl[kc], vbh[2], vbh[3]);
            }
        }
        __syncthreads();
    }

    float inv0 = 1.f / lrow[0];
    float inv1 = 1.f / lrow[1];
    size_t row0 = (size_t)b * TT + qblk * 64 + w * 16 + (lane >> 2);
    size_t row1 = row0 + 8;
    #pragma unroll
    for (int nt = 0; nt < 8; nt++) {
        int col = h * HDIM + nt * 8 + (lane & 3) * 2;
        float a0 = oacc[nt][0] * inv0;
        float a1 = oacc[nt][1] * inv0;
        float c0 = oacc[nt][2] * inv1;
        float c1 = oacc[nt][3] * inv1;
        __nv_bfloat16 ah0 = __float2bfloat16(a0);
        __nv_bfloat16 ah1 = __float2bfloat16(a1);
        __nv_bfloat16 ch0 = __float2bfloat16(c0);
        __nv_bfloat16 ch1 = __float2bfloat16(c1);
        *(u32*)(Oh + row0 * EE + col) = packbf(a0, a1);
        *(u32*)(Ol + row0 * EE + col) = packbf(a0 - __bfloat162float(ah0), a1 - __bfloat162float(ah1));
        *(u32*)(Oh + row1 * EE + col) = packbf(c0, c1);
        *(u32*)(Ol + row1 * EE + col) = packbf(c0 - __bfloat162float(ch0), c1 - __bfloat162float(ch1));
    }
}

// ---------------------------------------------------------------------------
// Launch helpers
// ---------------------------------------------------------------------------
static void run_gemm(int epi,
                     const __nv_bfloat16* Ah, const __nv_bfloat16* Al,
                     const __nv_bfloat16* Bh, const __nv_bfloat16* Bl,
                     const float* bias, float* C,
                     __nv_bfloat16* Ch, __nv_bfloat16* Cl,
                     int M, int N, int K)
{
    dim3 grid(N / 128, M / 128);
    if (epi == 1) {
        cudaFuncSetAttribute(tgemm_kernel<1>, cudaFuncAttributeMaxDynamicSharedMemorySize, SMEM_BYTES);
        tgemm_kernel<1><<<grid, 256, SMEM_BYTES>>>(Ah, Al, Bh, Bl, bias, C, Ch, Cl, M, N, K);
    } else if (epi == 2) {
        cudaFuncSetAttribute(tgemm_kernel<2>, cudaFuncAttributeMaxDynamicSharedMemorySize, SMEM_BYTES);
        tgemm_kernel<2><<<grid, 256, SMEM_BYTES>>>(Ah, Al, Bh, Bl, bias, C, Ch, Cl, M, N, K);
    } else {
        cudaFuncSetAttribute(tgemm_kernel<3>, cudaFuncAttributeMaxDynamicSharedMemorySize, SMEM_BYTES);
        tgemm_kernel<3><<<grid, 256, SMEM_BYTES>>>(Ah, Al, Bh, Bl, bias, C, Ch, Cl, M, N, K);
    }
}

static void run_split(const float* in, __nv_bfloat16* hi, __nv_bfloat16* lo, size_t n)
{
    split_kernel<<<(unsigned)(n / 1024), 256>>>(in, hi, lo);
}

static void run_attn(bool causal,
                     const __nv_bfloat16* qh, const __nv_bfloat16* ql,
                     const __nv_bfloat16* kh, const __nv_bfloat16* kl,
                     const __nv_bfloat16* vh, const __nv_bfloat16* vl,
                     __nv_bfloat16* oh, __nv_bfloat16* ol)
{
    dim3 grid(TT / 64, HH, BB);
    if (causal) {
        cudaFuncSetAttribute(attn_mma_kernel<true>, cudaFuncAttributeMaxDynamicSharedMemorySize, ATTN_SMEM);
        attn_mma_kernel<true><<<grid, 128, ATTN_SMEM>>>(qh, ql, kh, kl, vh, vl, oh, ol);
    } else {
        cudaFuncSetAttribute(attn_mma_kernel<false>, cudaFuncAttributeMaxDynamicSharedMemorySize, ATTN_SMEM);
        attn_mma_kernel<false><<<grid, 128, ATTN_SMEM>>>(qh, ql, kh, kl, vh, vl, oh, ol);
    }
}

extern "C" void kernel_launch(void* const* d_in, const int* in_sizes, int n_in,
                              void* d_out, int out_size)
{
    const float* enc   = (const float*)d_in[0];
    const float* dec   = (const float*)d_in[1];
    const float* ln1_w = (const float*)d_in[2];
    const float* ln1_b = (const float*)d_in[3];
    const float* ln2_w = (const float*)d_in[4];
    const float* ln2_b = (const float*)d_in[5];
    const float* ln3_w = (const float*)d_in[6];
    const float* ln3_b = (const float*)d_in[7];
    const float* Wq_s  = (const float*)d_in[8];
    const float* Wk_s  = (const float*)d_in[9];
    const float* Wv_s  = (const float*)d_in[10];
    const float* Wo_s  = (const float*)d_in[11];
    const float* bo_s  = (const float*)d_in[12];
    const float* Wq_c  = (const float*)d_in[13];
    const float* Wk_c  = (const float*)d_in[14];
    const float* Wv_c  = (const float*)d_in[15];
    const float* Wo_c  = (const float*)d_in[16];
    const float* bo_c  = (const float*)d_in[17];
    const float* W1    = (const float*)d_in[18];
    const float* b1p   = (const float*)d_in[19];
    const float* W2    = (const float*)d_in[20];
    const float* b2p   = (const float*)d_in[21];

    __nv_bfloat16 *qh, *ql, *kh, *kl, *vh, *vl;
    __nv_bfloat16 *nxh, *nxl, *ench, *encl, *ath, *atl, *ffh, *ffl, *wh, *wl;
    cudaGetSymbolAddress((void**)&qh,   g_qh);
    cudaGetSymbolAddress((void**)&ql,   g_ql);
    cudaGetSymbolAddress((void**)&kh,   g_kh);
    cudaGetSymbolAddress((void**)&kl,   g_kl);
    cudaGetSymbolAddress((void**)&vh,   g_vh);
    cudaGetSymbolAddress((void**)&vl,   g_vl);
    cudaGetSymbolAddress((void**)&nxh,  g_nxh);
    cudaGetSymbolAddress((void**)&nxl,  g_nxl);
    cudaGetSymbolAddress((void**)&ench, g_ench);
    cudaGetSymbolAddress((void**)&encl, g_encl);
    cudaGetSymbolAddress((void**)&ath,  g_ath);
    cudaGetSymbolAddress((void**)&atl,  g_atl);
    cudaGetSymbolAddress((void**)&ffh,  g_ffh);
    cudaGetSymbolAddress((void**)&ffl,  g_ffl);
    cudaGetSymbolAddress((void**)&wh,   g_wh);
    cudaGetSymbolAddress((void**)&wl,   g_wl);

    float* x = (float*)d_out;

    cudaMemcpyAsync(x, dec, (size_t)MROWS * EE * sizeof(float),
                    cudaMemcpyDeviceToDevice);

    run_split(enc, ench, encl, (size_t)MROWS * EE);

    for (int l = 0; l < LNUM; l++) {
        const size_t wE  = (size_t)l * EE * EE;
        const size_t wF1 = (size_t)l * EE * FF;
        const size_t wF2 = (size_t)l * FF * EE;

        // ---- self attention ----
        layernorm_kernel<<<MROWS, 256>>>(x, ln1_w + l * EE, ln1_b + l * EE, nxh, nxl);
        run_split(Wq_s + wE, wh, wl, (size_t)EE * EE);
        run_gemm(3, nxh, nxl, wh, wl, 0, 0, qh, ql, MROWS, EE, EE);
        run_split(Wk_s + wE, wh, wl, (size_t)EE * EE);
        run_gemm(3, nxh, nxl, wh, wl, 0, 0, kh, kl, MROWS, EE, EE);
        run_split(Wv_s + wE, wh, wl, (size_t)EE * EE);
        run_gemm(3, nxh, nxl, wh, wl, 0, 0, vh, vl, MROWS, EE, EE);
        run_attn(true, qh, ql, kh, kl, vh, vl, ath, atl);
        run_split(Wo_s + wE, wh, wl, (size_t)EE * EE);
        run_gemm(2, ath, atl, wh, wl, bo_s + l * EE, x, 0, 0, MROWS, EE, EE);

        // ---- cross attention ----
        layernorm_kernel<<<MROWS, 256>>>(x, ln2_w + l * EE, ln2_b + l * EE, nxh, nxl);
        run_split(Wq_c + wE, wh, wl, (size_t)EE * EE);
        run_gemm(3, nxh, nxl, wh, wl, 0, 0, qh, ql, MROWS, EE, EE);
        run_split(Wk_c + wE, wh, wl, (size_t)EE * EE);
        run_gemm(3, ench, encl, wh, wl, 0, 0, kh, kl, MROWS, EE, EE);
        run_split(Wv_c + wE, wh, wl, (size_t)EE * EE);
        run_gemm(3, ench, encl, wh, wl, 0, 0, vh, vl, MROWS, EE, EE);
        run_attn(false, qh, ql, kh, kl, vh, vl, ath, atl);
        run_split(Wo_c + wE, wh, wl, (size_t)EE * EE);
        run_gemm(2, ath, atl, wh, wl, bo_c + l * EE, x, 0, 0, MROWS, EE, EE);

        // ---- FFN ----
        layernorm_kernel<<<MROWS, 256>>>(x, ln3_w + l * EE, ln3_b + l * EE, nxh, nxl);
        run_split(W1 + wF1, wh, wl, (size_t)EE * FF);
        run_gemm(1, nxh, nxl, wh, wl, b1p + (size_t)l * FF, 0, ffh, ffl, MROWS, FF, EE);
        run_split(W2 + wF2, wh, wl, (size_t)FF * EE);
        run_gemm(2, ffh, ffl, wh, wl, b2p + (size_t)l * EE, x, 0, 0, MROWS, EE, FF);
    }
}